// round 1
// baseline (speedup 1.0000x reference)
#include <cuda_runtime.h>

#define NROW 512
#define HH 8
#define DD 32
#define INNER 256
#define ED 64
#define SCALE 0.17677669529663687f  // 1/sqrt(32)

// Scratch (device globals; no allocation in kernel_launch).
__device__ float g_q[NROW * INNER];
__device__ float g_k[NROW * INNER];
__device__ float g_v[NROW * INNER];
__device__ float g_t[NROW * HH * ED];      // [i][h][c]  t = We_h^T q_{h,i}
__device__ float g_qbe[NROW * HH];         // q_{h,i} . be_h
__device__ float g_simqk[HH * NROW * NROW];
__device__ float g_attn[HH * NROW * NROW];
__device__ float g_agg[NROW * HH * ED];    // [i][h][c]
__device__ float g_rowsum[HH * NROW];      // 1 if any neighbor, else 0

// ---------------------------------------------------------------------------
// Kernel A: q/k/v projections + t = We_h^T q + qbe.  4 rows per block.
// ---------------------------------------------------------------------------
__global__ __launch_bounds__(256) void proj_kernel(
    const float* __restrict__ nodes,
    const float* __restrict__ Wq, const float* __restrict__ bq,
    const float* __restrict__ Wk, const float* __restrict__ bk,
    const float* __restrict__ Wv, const float* __restrict__ bv,
    const float* __restrict__ We, const float* __restrict__ be)
{
    __shared__ float node_s[4][128];
    __shared__ float q_s[4][INNER];
    const int t = threadIdx.x;
    const int i0 = blockIdx.x * 4;

    for (int idx = t; idx < 4 * 128; idx += 256)
        node_s[idx >> 7][idx & 127] = nodes[i0 * 128 + idx];
    __syncthreads();

    float aq[4], ak[4], av[4];
    const float bqv = bq[t], bkv = bk[t], bvv = bv[t];
#pragma unroll
    for (int r = 0; r < 4; r++) { aq[r] = bqv; ak[r] = bkv; av[r] = bvv; }

    for (int k = 0; k < 128; k++) {
        const float wq = Wq[k * INNER + t];
        const float wk = Wk[k * INNER + t];
        const float wv = Wv[k * INNER + t];
#pragma unroll
        for (int r = 0; r < 4; r++) {
            const float nv = node_s[r][k];
            aq[r] = fmaf(nv, wq, aq[r]);
            ak[r] = fmaf(nv, wk, ak[r]);
            av[r] = fmaf(nv, wv, av[r]);
        }
    }
#pragma unroll
    for (int r = 0; r < 4; r++) {
        g_q[(i0 + r) * INNER + t] = aq[r];
        g_k[(i0 + r) * INNER + t] = ak[r];
        g_v[(i0 + r) * INNER + t] = av[r];
        q_s[r][t] = aq[r];
    }
    __syncthreads();

    // t[i][h][c] = sum_d We[c, h*32+d] * q[i, h*32+d]
    for (int idx = t; idx < HH * ED; idx += 256) {
        const int h = idx >> 6, c = idx & 63;
        float acc[4] = {0.f, 0.f, 0.f, 0.f};
        const float* wrow = We + c * INNER + h * DD;
#pragma unroll
        for (int d = 0; d < DD; d++) {
            const float w = wrow[d];
#pragma unroll
            for (int r = 0; r < 4; r++)
                acc[r] = fmaf(w, q_s[r][h * DD + d], acc[r]);
        }
#pragma unroll
        for (int r = 0; r < 4; r++)
            g_t[(i0 + r) * (HH * ED) + idx] = acc[r];
    }

    if (t < 4 * HH) {
        const int r = t >> 3, h = t & 7;
        float s = 0.f;
#pragma unroll
        for (int d = 0; d < DD; d++)
            s = fmaf(q_s[r][h * DD + d], be[h * DD + d], s);
        g_qbe[(i0 + r) * HH + h] = s;
    }
}

// ---------------------------------------------------------------------------
// Kernel QK: simqk[h][i][j] = (q_h[i].k_h[j] + qbe[i][h]) * SCALE
// grid (16, 16, 8): 32x32 tiles per head, K = 32 in one shot.
// ---------------------------------------------------------------------------
__global__ __launch_bounds__(256) void qk_kernel()
{
    __shared__ float q_s[32][33];
    __shared__ float k_s[32][33];
    const int t = threadIdx.x;
    const int j0 = blockIdx.x * 32;
    const int i0 = blockIdx.y * 32;
    const int h  = blockIdx.z;

    {
        const int r = t >> 3, c4 = (t & 7) * 4;
        const float4 qv = *(const float4*)&g_q[(i0 + r) * INNER + h * DD + c4];
        q_s[r][c4 + 0] = qv.x; q_s[r][c4 + 1] = qv.y;
        q_s[r][c4 + 2] = qv.z; q_s[r][c4 + 3] = qv.w;
        const float4 kv = *(const float4*)&g_k[(j0 + r) * INNER + h * DD + c4];
        k_s[r][c4 + 0] = kv.x; k_s[r][c4 + 1] = kv.y;
        k_s[r][c4 + 2] = kv.z; k_s[r][c4 + 3] = kv.w;
    }
    __syncthreads();

    const int tx = t & 31, ty = t >> 5;
    float acc[4] = {0.f, 0.f, 0.f, 0.f};
#pragma unroll
    for (int d = 0; d < 32; d++) {
        const float kv = k_s[tx][d];
#pragma unroll
        for (int m = 0; m < 4; m++)
            acc[m] = fmaf(q_s[ty + m * 8][d], kv, acc[m]);
    }
#pragma unroll
    for (int m = 0; m < 4; m++) {
        const int i = i0 + ty + m * 8;
        g_simqk[((size_t)h * NROW + i) * NROW + j0 + tx] =
            (acc[m] + g_qbe[i * HH + h]) * SCALE;
    }
}

// ---------------------------------------------------------------------------
// Kernel B: per node-row i — edge scores + softmax + edge aggregation.
// One block per row (512 blocks, 256 threads).
// ---------------------------------------------------------------------------
__global__ __launch_bounds__(256) void attn_kernel(
    const float* __restrict__ edges, const int* __restrict__ adj)
{
    __shared__ __align__(16) float t_s[HH * 68];      // padded (68 = odd*4) for conflict-free f4
    __shared__ float sim_s[HH * NROW];                // sim, then attn (16 KB)
    __shared__ __align__(16) float e_s[64 * 68];      // edge chunk (64 j x 64 c, stride 68)

    const int t = threadIdx.x;
    const int i = blockIdx.x;

    for (int idx = t; idx < HH * ED; idx += 256)
        t_s[(idx >> 6) * 68 + (idx & 63)] = g_t[i * (HH * ED) + idx];

    const int hh  = t >> 6;       // 0..3 (each thread does heads hh and hh+4)
    const int jj  = t & 63;
    const int c4l = t & 15;       // loader coords
    const int jjl = t >> 4;

    // ---- pass 1: sim[h][j] = (edges_ij . t[h]) * SCALE + simqk ----
    for (int ch = 0; ch < 8; ch++) {
        __syncthreads();
        const int j0 = ch * 64;
#pragma unroll
        for (int p = 0; p < 4; p++) {
            const int row = jjl + p * 16;
            *(float4*)&e_s[row * 68 + c4l * 4] =
                *(const float4*)&edges[((size_t)(i * NROW) + j0 + row) * ED + c4l * 4];
        }
        __syncthreads();

        float acc0 = 0.f, acc1 = 0.f;
        const float4* ep  = (const float4*)&e_s[jj * 68];
        const float4* ta4 = (const float4*)&t_s[hh * 68];
        const float4* tb4 = (const float4*)&t_s[(hh + 4) * 68];
#pragma unroll
        for (int c = 0; c < 16; c++) {
            const float4 e4 = ep[c];
            const float4 ta = ta4[c];
            const float4 tb = tb4[c];
            acc0 = fmaf(e4.x, ta.x, acc0); acc0 = fmaf(e4.y, ta.y, acc0);
            acc0 = fmaf(e4.z, ta.z, acc0); acc0 = fmaf(e4.w, ta.w, acc0);
            acc1 = fmaf(e4.x, tb.x, acc1); acc1 = fmaf(e4.y, tb.y, acc1);
            acc1 = fmaf(e4.z, tb.z, acc1); acc1 = fmaf(e4.w, tb.w, acc1);
        }
        const int j = j0 + jj;
        sim_s[hh * NROW + j] =
            fmaf(acc0, SCALE, g_simqk[((size_t)hh * NROW + i) * NROW + j]);
        sim_s[(hh + 4) * NROW + j] =
            fmaf(acc1, SCALE, g_simqk[((size_t)(hh + 4) * NROW + i) * NROW + j]);
    }
    __syncthreads();

    // ---- softmax. Reference's mean-shift is row-constant -> cancels exactly.
    //      Values are O(0.1), exp is safe unshifted. ----
    {
        const int h = t >> 5, lane = t & 31;   // one warp per head
        float part = 0.f;
#pragma unroll
        for (int k = 0; k < 16; k++) {
            const int j = lane + k * 32;
            const float s = sim_s[h * NROW + j];
            const int a = adj[i * NROW + j];
            const float ex = a ? __expf(s) : 0.f;
            sim_s[h * NROW + j] = ex;
            part += ex;
        }
#pragma unroll
        for (int o = 16; o > 0; o >>= 1)
            part += __shfl_xor_sync(0xffffffffu, part, o);
        const float inv = part > 0.f ? 1.f / part : 0.f;
        if (lane == 0) g_rowsum[h * NROW + i] = part > 0.f ? 1.f : 0.f;
#pragma unroll
        for (int k = 0; k < 16; k++) {
            const int j = lane + k * 32;
            const float a = sim_s[h * NROW + j] * inv;
            sim_s[h * NROW + j] = a;
            g_attn[((size_t)h * NROW + i) * NROW + j] = a;
        }
    }

    // ---- pass 2: agg[h][c] = sum_j attn[h][j] * edges[i][j][c]
    //      all 8 heads kept in registers -> each edge element read ONCE. ----
    float4 acc[8];
#pragma unroll
    for (int h = 0; h < 8; h++) acc[h] = make_float4(0.f, 0.f, 0.f, 0.f);
    const int c4 = t & 15;
    const int jo = t >> 4;        // 16 j-slices -> reduced at the end

    for (int ch = 0; ch < 8; ch++) {
        __syncthreads();
        const int j0 = ch * 64;
#pragma unroll
        for (int p = 0; p < 4; p++) {
            const int row = jjl + p * 16;
            *(float4*)&e_s[row * 68 + c4l * 4] =
                *(const float4*)&edges[((size_t)(i * NROW) + j0 + row) * ED + c4l * 4];
        }
        __syncthreads();
#pragma unroll
        for (int kk = 0; kk < 4; kk++) {
            const int jjx = jo + kk * 16;
            const int j = j0 + jjx;
            const float4 e4 = *(const float4*)&e_s[jjx * 68 + c4 * 4];
#pragma unroll
            for (int h = 0; h < 8; h++) {
                const float a = sim_s[h * NROW + j];
                acc[h].x = fmaf(a, e4.x, acc[h].x);
                acc[h].y = fmaf(a, e4.y, acc[h].y);
                acc[h].z = fmaf(a, e4.z, acc[h].z);
                acc[h].w = fmaf(a, e4.w, acc[h].w);
            }
        }
    }

    // reduce the 16 jo-partials (tree, reusing e_s)
    float* buf = e_s;
    for (int s = 8; s >= 1; s >>= 1) {
        __syncthreads();
        if (jo >= s && jo < 2 * s) {
            float* b = &buf[((jo - s) * 16 + c4) * 32];
#pragma unroll
            for (int h = 0; h < 8; h++) {
                b[h * 4 + 0] = acc[h].x; b[h * 4 + 1] = acc[h].y;
                b[h * 4 + 2] = acc[h].z; b[h * 4 + 3] = acc[h].w;
            }
        }
        __syncthreads();
        if (jo < s) {
            const float* b = &buf[(jo * 16 + c4) * 32];
#pragma unroll
            for (int h = 0; h < 8; h++) {
                acc[h].x += b[h * 4 + 0]; acc[h].y += b[h * 4 + 1];
                acc[h].z += b[h * 4 + 2]; acc[h].w += b[h * 4 + 3];
            }
        }
    }
    if (jo == 0) {
#pragma unroll
        for (int h = 0; h < 8; h++)
            *(float4*)&g_agg[i * (HH * ED) + h * ED + c4 * 4] = acc[h];
    }
}

// ---------------------------------------------------------------------------
// Kernel C: out = attn @ v  +  agg @ We  +  rowsum * be
// grid (16 i-tiles of 32, 8 heads), 256 threads, 4 rows per thread.
// ---------------------------------------------------------------------------
__global__ __launch_bounds__(256) void out_kernel(
    const float* __restrict__ We, const float* __restrict__ be,
    float* __restrict__ out)
{
    __shared__ float a_s[32 * 64];
    __shared__ float v_s[64 * 32];
    const int t = threadIdx.x;
    const int i0 = blockIdx.x * 32;
    const int h  = blockIdx.y;
    const int d  = t & 31;
    const int i4 = t >> 5;
    float acc[4] = {0.f, 0.f, 0.f, 0.f};

    for (int jt = 0; jt < 8; jt++) {
        const int j0 = jt * 64;
        __syncthreads();
#pragma unroll
        for (int f = 0; f < 2; f++) {
            const int idx = t * 2 + f;          // 512 float4s: attn 32x64
            const int row = idx >> 4, c4 = idx & 15;
            *(float4*)&a_s[row * 64 + c4 * 4] =
                *(const float4*)&g_attn[((size_t)h * NROW + i0 + row) * NROW + j0 + c4 * 4];
        }
#pragma unroll
        for (int f = 0; f < 2; f++) {
            const int idx = t * 2 + f;          // 512 float4s: v 64x32
            const int row = idx >> 3, c4 = idx & 7;
            *(float4*)&v_s[row * 32 + c4 * 4] =
                *(const float4*)&g_v[(j0 + row) * INNER + h * DD + c4 * 4];
        }
        __syncthreads();
#pragma unroll 8
        for (int jl = 0; jl < 64; jl++) {
            const float vv = v_s[jl * 32 + d];
#pragma unroll
            for (int m = 0; m < 4; m++)
                acc[m] = fmaf(a_s[(i4 + m * 8) * 64 + jl], vv, acc[m]);
        }
    }

    // edge contribution: agg @ We
    __syncthreads();
#pragma unroll
    for (int f = 0; f < 2; f++) {
        const int idx = t * 2 + f;
        const int row = idx >> 4, c4 = idx & 15;
        *(float4*)&a_s[row * 64 + c4 * 4] =
            *(const float4*)&g_agg[(i0 + row) * (HH * ED) + h * ED + c4 * 4];
    }
    __syncthreads();
#pragma unroll 8
    for (int c = 0; c < 64; c++) {
        const float w = We[c * INNER + h * DD + d];
#pragma unroll
        for (int m = 0; m < 4; m++)
            acc[m] = fmaf(a_s[(i4 + m * 8) * 64 + c], w, acc[m]);
    }

    const float bev = be[h * DD + d];
#pragma unroll
    for (int m = 0; m < 4; m++) {
        const int i = i0 + i4 + m * 8;
        const float rs = g_rowsum[h * NROW + i];
        out[i * INNER + h * DD + d] = fmaf(rs, bev, acc[m]);
    }
}

// ---------------------------------------------------------------------------
extern "C" void kernel_launch(void* const* d_in, const int* in_sizes, int n_in,
                              void* d_out, int out_size)
{
    const float* nodes = (const float*)d_in[0];
    const float* edges = (const float*)d_in[1];
    const int*   adj   = (const int*)d_in[2];
    const float* Wq    = (const float*)d_in[3];
    const float* bq    = (const float*)d_in[4];
    const float* Wk    = (const float*)d_in[5];
    const float* bk    = (const float*)d_in[6];
    const float* Wv    = (const float*)d_in[7];
    const float* bv    = (const float*)d_in[8];
    const float* We    = (const float*)d_in[9];
    const float* be    = (const float*)d_in[10];
    float* out = (float*)d_out;

    proj_kernel<<<128, 256>>>(nodes, Wq, bq, Wk, bk, Wv, bv, We, be);
    qk_kernel<<<dim3(16, 16, 8), 256>>>();
    attn_kernel<<<512, 256>>>(edges, adj);
    out_kernel<<<dim3(16, 8), 256>>>(We, be, out);
}